// round 1
// baseline (speedup 1.0000x reference)
#include <cuda_runtime.h>

#define IN_DIM   8192
#define OUT_DIM  16384
#define B_ROWS   2048

constexpr int THREADS         = 512;
constexpr int ROWS_PER_CTA    = 4;
constexpr int COLS_PER_CTA    = 4096;
constexpr int COLS_PER_THREAD = COLS_PER_CTA / THREADS;  // 8
constexpr int SMEM_BYTES      = ROWS_PER_CTA * IN_DIM * (int)sizeof(float);  // 128 KB

// Precomputed per-output-column coefficients: out = c.x + c.y*a + c.z*b + c.w*a*b
__device__ float4 g_coef[OUT_DIM];

// ---------------------------------------------------------------------------
// Kernel 1: softmax(weights[o, 0..15]) -> affine coefficients in {1, a, b, ab}
// ---------------------------------------------------------------------------
__global__ void coef_kernel(const float* __restrict__ w)
{
    int o = blockIdx.x * blockDim.x + threadIdx.x;
    if (o >= OUT_DIM) return;

    float v[16];
    float m = -1e30f;
#pragma unroll
    for (int i = 0; i < 16; i++) {
        v[i] = w[o * 16 + i];
        m = fmaxf(m, v[i]);
    }
    float s = 0.0f;
#pragma unroll
    for (int i = 0; i < 16; i++) {
        v[i] = expf(v[i] - m);
        s += v[i];
    }
    float inv = 1.0f / s;
#pragma unroll
    for (int i = 0; i < 16; i++) v[i] *= inv;

    // Gate table (difflogic order):
    //  1: ab            2: a-ab        3: a          4: b-ab       5: b
    //  6: a+b-2ab       7: a+b-ab      8: 1-(a+b-ab) 9: 1-(a+b-2ab)
    // 10: 1-b          11: 1-b+ab     12: 1-a       13: 1-a+ab
    // 14: 1-ab         15: 1           (gate 0 == 0, weight unused)
    float c1  = v[8] + v[9] + v[10] + v[11] + v[12] + v[13] + v[14] + v[15];
    float ca  = v[2] + v[3] + v[6] + v[7] - v[8] - v[9] - v[12] - v[13];
    float cb  = v[4] + v[5] + v[6] + v[7] - v[8] - v[9] - v[10] - v[11];
    float cab = v[1] - v[2] - v[4] - 2.0f * v[6] - v[7]
              + v[8] + 2.0f * v[9] + v[11] + v[13] - v[14];

    g_coef[o] = make_float4(c1, ca, cb, cab);
}

// ---------------------------------------------------------------------------
// Kernel 2: main gather + affine evaluation.
// CTA = (4 batch rows staged in smem) x (4096 output columns).
// ---------------------------------------------------------------------------
__global__ __launch_bounds__(THREADS)
void logic_kernel(const float* __restrict__ x,
                  const int*   __restrict__ idx_a,
                  const int*   __restrict__ idx_b,
                  float*       __restrict__ out)
{
    extern __shared__ float sx[];  // [ROWS_PER_CTA][IN_DIM]

    const int row0 = blockIdx.y * ROWS_PER_CTA;
    const int col0 = blockIdx.x * COLS_PER_CTA;

    // Stage 4 contiguous x rows into shared memory (coalesced float4 loads).
    {
        const float4* xg = reinterpret_cast<const float4*>(x + (size_t)row0 * IN_DIM);
        float4* sg = reinterpret_cast<float4*>(sx);
        constexpr int N4 = ROWS_PER_CTA * IN_DIM / 4;  // 8192
#pragma unroll
        for (int i = threadIdx.x; i < N4; i += THREADS)
            sg[i] = xg[i];
    }
    __syncthreads();

#pragma unroll
    for (int c = 0; c < COLS_PER_THREAD; c++) {
        const int col = col0 + c * THREADS + threadIdx.x;
        const int ia = idx_a[col];
        const int ib = idx_b[col];
        const float4 cf = g_coef[col];

        float* o0 = out + (size_t)row0 * OUT_DIM + col;
#pragma unroll
        for (int r = 0; r < ROWS_PER_CTA; r++) {
            float a = sx[r * IN_DIM + ia];
            float b = sx[r * IN_DIM + ib];
            float res = fmaf(cf.w, a * b, fmaf(cf.z, b, fmaf(cf.y, a, cf.x)));
            o0[(size_t)r * OUT_DIM] = res;
        }
    }
}

// ---------------------------------------------------------------------------
// Launch
// ---------------------------------------------------------------------------
extern "C" void kernel_launch(void* const* d_in, const int* in_sizes, int n_in,
                              void* d_out, int out_size)
{
    const float* x  = (const float*)d_in[0];   // [2048, 8192] f32
    const float* w  = (const float*)d_in[1];   // [16384, 16]  f32
    const int*   ia = (const int*)d_in[2];     // [16384] i32
    const int*   ib = (const int*)d_in[3];     // [16384] i32
    float*       out = (float*)d_out;          // [2048, 16384] f32

    coef_kernel<<<OUT_DIM / 256, 256>>>(w);

    cudaFuncSetAttribute(logic_kernel,
                         cudaFuncAttributeMaxDynamicSharedMemorySize, SMEM_BYTES);

    dim3 grid(OUT_DIM / COLS_PER_CTA, B_ROWS / ROWS_PER_CTA);  // (4, 512)
    logic_kernel<<<grid, THREADS, SMEM_BYTES>>>(x, ia, ib, out);
}

// round 2
// speedup vs baseline: 1.3202x; 1.3202x over previous
#include <cuda_runtime.h>

#define IN_DIM   8192
#define OUT_DIM  16384
#define B_ROWS   2048

constexpr int THREADS         = 1024;
constexpr int ROWS_PER_CTA    = 4;                       // float4 of rows per smem slot
constexpr int COLS_PER_CTA    = 8192;
constexpr int COLS_PER_THREAD = COLS_PER_CTA / THREADS;  // 8
constexpr int SMEM_BYTES      = IN_DIM * ROWS_PER_CTA * (int)sizeof(float);  // 128 KB

// Precomputed per-output-column coefficients: out = c.x + c.y*a + c.z*b + c.w*a*b
__device__ float4 g_coef[OUT_DIM];

// ---------------------------------------------------------------------------
// Kernel 1: softmax(weights[o, 0..15]) -> affine coefficients in {1, a, b, ab}
// ---------------------------------------------------------------------------
__global__ void coef_kernel(const float* __restrict__ w)
{
    int o = blockIdx.x * blockDim.x + threadIdx.x;
    if (o >= OUT_DIM) return;

    float v[16];
    float m = -1e30f;
#pragma unroll
    for (int i = 0; i < 16; i++) {
        v[i] = w[o * 16 + i];
        m = fmaxf(m, v[i]);
    }
    float s = 0.0f;
#pragma unroll
    for (int i = 0; i < 16; i++) {
        v[i] = expf(v[i] - m);
        s += v[i];
    }
    float inv = 1.0f / s;
#pragma unroll
    for (int i = 0; i < 16; i++) v[i] *= inv;

    // Gate table (difflogic order); gate 0 == 0 so v[0] unused.
    float c1  = v[8] + v[9] + v[10] + v[11] + v[12] + v[13] + v[14] + v[15];
    float ca  = v[2] + v[3] + v[6] + v[7] - v[8] - v[9] - v[12] - v[13];
    float cb  = v[4] + v[5] + v[6] + v[7] - v[8] - v[9] - v[10] - v[11];
    float cab = v[1] - v[2] - v[4] - 2.0f * v[6] - v[7]
              + v[8] + 2.0f * v[9] + v[11] + v[13] - v[14];

    g_coef[o] = make_float4(c1, ca, cb, cab);
}

// ---------------------------------------------------------------------------
// Kernel 2: gather + affine eval with row-transposed smem (float4 = 4 rows).
// ---------------------------------------------------------------------------
__global__ __launch_bounds__(THREADS, 1)
void logic_kernel(const float* __restrict__ x,
                  const int*   __restrict__ idx_a,
                  const int*   __restrict__ idx_b,
                  float*       __restrict__ out)
{
    extern __shared__ float4 sx4[];  // sx4[in_col] = {row0, row1, row2, row3}

    const int row0 = blockIdx.y * ROWS_PER_CTA;
    const int col0 = blockIdx.x * COLS_PER_CTA;
    const int lane = threadIdx.x & 31;
    const int warp = threadIdx.x >> 5;
    constexpr int NWARPS = THREADS / 32;

    // Transposed staging: per 32-column group, 4 coalesced row loads,
    // then one contiguous STS.128 per lane (conflict-free).
    const float* xb = x + (size_t)row0 * IN_DIM;
#pragma unroll
    for (int g = warp; g < IN_DIM / 32; g += NWARPS) {
        int col = g * 32 + lane;
        float r0 = xb[0 * IN_DIM + col];
        float r1 = xb[1 * IN_DIM + col];
        float r2 = xb[2 * IN_DIM + col];
        float r3 = xb[3 * IN_DIM + col];
        sx4[col] = make_float4(r0, r1, r2, r3);
    }
    __syncthreads();

#pragma unroll
    for (int c = 0; c < COLS_PER_THREAD; c++) {
        const int col = col0 + c * THREADS + threadIdx.x;
        const int ia = idx_a[col];
        const int ib = idx_b[col];
        const float4 cf = g_coef[col];

        const float4 a = sx4[ia];   // 4 batch rows in one LDS.128
        const float4 b = sx4[ib];

        float* o0 = out + (size_t)row0 * OUT_DIM + col;
        o0[0 * (size_t)OUT_DIM] = fmaf(cf.w, a.x * b.x, fmaf(cf.z, b.x, fmaf(cf.y, a.x, cf.x)));
        o0[1 * (size_t)OUT_DIM] = fmaf(cf.w, a.y * b.y, fmaf(cf.z, b.y, fmaf(cf.y, a.y, cf.x)));
        o0[2 * (size_t)OUT_DIM] = fmaf(cf.w, a.z * b.z, fmaf(cf.z, b.z, fmaf(cf.y, a.z, cf.x)));
        o0[3 * (size_t)OUT_DIM] = fmaf(cf.w, a.w * b.w, fmaf(cf.z, b.w, fmaf(cf.y, a.w, cf.x)));
    }
}

// ---------------------------------------------------------------------------
// Launch
// ---------------------------------------------------------------------------
extern "C" void kernel_launch(void* const* d_in, const int* in_sizes, int n_in,
                              void* d_out, int out_size)
{
    const float* x  = (const float*)d_in[0];   // [2048, 8192] f32
    const float* w  = (const float*)d_in[1];   // [16384, 16]  f32
    const int*   ia = (const int*)d_in[2];     // [16384] i32
    const int*   ib = (const int*)d_in[3];     // [16384] i32
    float*       out = (float*)d_out;          // [2048, 16384] f32

    coef_kernel<<<OUT_DIM / 256, 256>>>(w);

    cudaFuncSetAttribute(logic_kernel,
                         cudaFuncAttributeMaxDynamicSharedMemorySize, SMEM_BYTES);

    dim3 grid(OUT_DIM / COLS_PER_CTA, B_ROWS / ROWS_PER_CTA);  // (2, 512)
    logic_kernel<<<grid, THREADS, SMEM_BYTES>>>(x, ia, ib, out);
}

// round 4
// speedup vs baseline: 1.4165x; 1.0730x over previous
#include <cuda_runtime.h>
#include <cuda_fp16.h>

#define IN_DIM   8192
#define OUT_DIM  16384
#define B_ROWS   2048

constexpr int THREADS         = 1024;
constexpr int ROWS_PER_CTA    = 8;                       // 8 fp16 rows per 16B smem slot
constexpr int COLS_PER_CTA    = 8192;
constexpr int COLS_PER_THREAD = COLS_PER_CTA / THREADS;  // 8
constexpr int SMEM_BYTES      = IN_DIM * ROWS_PER_CTA * 2;  // 128 KB

// 16-byte slot holding 8 fp16 batch rows of one input column.
struct alignas(16) H8 { half2 h[4]; };

// Precomputed per-output-column data.
__device__ float4 g_coef[OUT_DIM];   // out = c1 + ca*a + cb*b + cab*ab
__device__ int2   g_idx [OUT_DIM];   // {idx_a, idx_b}

// ---------------------------------------------------------------------------
// Kernel 1: softmax(weights) -> affine coefficients; pack idx pairs.
// ---------------------------------------------------------------------------
__global__ void coef_kernel(const float* __restrict__ w,
                            const int*   __restrict__ idx_a,
                            const int*   __restrict__ idx_b)
{
    int o = blockIdx.x * blockDim.x + threadIdx.x;
    if (o >= OUT_DIM) return;

    float v[16];
    float m = -1e30f;
#pragma unroll
    for (int i = 0; i < 16; i++) {
        v[i] = w[o * 16 + i];
        m = fmaxf(m, v[i]);
    }
    float s = 0.0f;
#pragma unroll
    for (int i = 0; i < 16; i++) {
        v[i] = expf(v[i] - m);
        s += v[i];
    }
    float inv = 1.0f / s;
#pragma unroll
    for (int i = 0; i < 16; i++) v[i] *= inv;

    // Gate table (difflogic order); gate 0 == 0 so v[0] unused.
    float c1  = v[8] + v[9] + v[10] + v[11] + v[12] + v[13] + v[14] + v[15];
    float ca  = v[2] + v[3] + v[6] + v[7] - v[8] - v[9] - v[12] - v[13];
    float cb  = v[4] + v[5] + v[6] + v[7] - v[8] - v[9] - v[10] - v[11];
    float cab = v[1] - v[2] - v[4] - 2.0f * v[6] - v[7]
              + v[8] + 2.0f * v[9] + v[11] + v[13] - v[14];

    g_coef[o] = make_float4(c1, ca, cb, cab);
    g_idx[o]  = make_int2(idx_a[o], idx_b[o]);
}

// ---------------------------------------------------------------------------
// Kernel 2: gather + affine eval. Smem slab: sx[in_col] = 8 fp16 batch rows.
// One LDS.128 fetches 8 rows of a gathered column.
// ---------------------------------------------------------------------------
__global__ __launch_bounds__(THREADS, 1)
void logic_kernel(const float* __restrict__ x,
                  float*       __restrict__ out)
{
    extern __shared__ H8 sx[];  // sx[col].h[p] = rows {2p, 2p+1} of column col

    const int row0 = blockIdx.y * ROWS_PER_CTA;
    const int col0 = blockIdx.x * COLS_PER_CTA;
    const int lane = threadIdx.x & 31;
    const int warp = threadIdx.x >> 5;
    constexpr int NWARPS = THREADS / 32;

    // Transposed fp16 staging: per 32-column group, 8 coalesced row loads,
    // convert to half, one contiguous STS.128 per lane (conflict-free).
    const float* xb = x + (size_t)row0 * IN_DIM;
#pragma unroll
    for (int g = warp; g < IN_DIM / 32; g += NWARPS) {
        int col = g * 32 + lane;
        H8 v;
#pragma unroll
        for (int p = 0; p < 4; p++) {
            v.h[p] = make_half2(__float2half_rn(xb[(size_t)(2 * p + 0) * IN_DIM + col]),
                                __float2half_rn(xb[(size_t)(2 * p + 1) * IN_DIM + col]));
        }
        sx[col] = v;
    }
    __syncthreads();

#pragma unroll
    for (int c = 0; c < COLS_PER_THREAD; c++) {
        const int col = col0 + c * THREADS + threadIdx.x;
        const int2   id = g_idx[col];
        const float4 cf = g_coef[col];

        const H8 a8 = sx[id.x];   // 8 batch rows of a in one LDS.128
        const H8 b8 = sx[id.y];

        float* o0 = out + (size_t)row0 * OUT_DIM + col;
#pragma unroll
        for (int p = 0; p < 4; p++) {
            float2 af = __half22float2(a8.h[p]);
            float2 bf = __half22float2(b8.h[p]);
            o0[(size_t)(2 * p + 0) * OUT_DIM] =
                fmaf(cf.w, af.x * bf.x, fmaf(cf.z, bf.x, fmaf(cf.y, af.x, cf.x)));
            o0[(size_t)(2 * p + 1) * OUT_DIM] =
                fmaf(cf.w, af.y * bf.y, fmaf(cf.z, bf.y, fmaf(cf.y, af.y, cf.x)));
        }
    }
}

// ---------------------------------------------------------------------------
// Launch
// ---------------------------------------------------------------------------
extern "C" void kernel_launch(void* const* d_in, const int* in_sizes, int n_in,
                              void* d_out, int out_size)
{
    const float* x  = (const float*)d_in[0];   // [2048, 8192] f32
    const float* w  = (const float*)d_in[1];   // [16384, 16]  f32
    const int*   ia = (const int*)d_in[2];     // [16384] i32
    const int*   ib = (const int*)d_in[3];     // [16384] i32
    float*       out = (float*)d_out;          // [2048, 16384] f32

    coef_kernel<<<OUT_DIM / 256, 256>>>(w, ia, ib);

    cudaFuncSetAttribute(logic_kernel,
                         cudaFuncAttributeMaxDynamicSharedMemorySize, SMEM_BYTES);

    dim3 grid(OUT_DIM / COLS_PER_CTA, B_ROWS / ROWS_PER_CTA);  // (2, 256)
    logic_kernel<<<grid, THREADS, SMEM_BYTES>>>(x, out);
}

// round 5
// speedup vs baseline: 1.4540x; 1.0264x over previous
#include <cuda_runtime.h>
#include <cuda_fp16.h>

#define IN_DIM   8192
#define OUT_DIM  16384
#define B_ROWS   2048

constexpr int THREADS         = 1024;
constexpr int ROWS_PER_CTA    = 8;                       // 8 fp16 rows per 16B smem slot
constexpr int COLS_PER_CTA    = 8192;
constexpr int COLS_PER_THREAD = COLS_PER_CTA / THREADS;  // 8
constexpr int SMEM_BYTES      = IN_DIM * ROWS_PER_CTA * 2;  // 128 KB

// 16-byte slot holding 8 fp16 batch rows of one input column.
struct alignas(16) H8 { half2 h[4]; };

// Precomputed per-output-column data.
__device__ float4 g_coef[OUT_DIM];   // out = c1 + ca*a + cb*b + cab*ab
__device__ int2   g_idx [OUT_DIM];   // {idx_a, idx_b}

// ---------------------------------------------------------------------------
// Kernel 1: softmax(weights) -> affine coefficients; pack idx pairs.
// ---------------------------------------------------------------------------
__global__ void coef_kernel(const float* __restrict__ w,
                            const int*   __restrict__ idx_a,
                            const int*   __restrict__ idx_b)
{
    int o = blockIdx.x * blockDim.x + threadIdx.x;
    if (o >= OUT_DIM) return;

    float v[16];
    float m = -1e30f;
#pragma unroll
    for (int i = 0; i < 16; i++) {
        v[i] = w[o * 16 + i];
        m = fmaxf(m, v[i]);
    }
    float s = 0.0f;
#pragma unroll
    for (int i = 0; i < 16; i++) {
        v[i] = expf(v[i] - m);
        s += v[i];
    }
    float inv = 1.0f / s;
#pragma unroll
    for (int i = 0; i < 16; i++) v[i] *= inv;

    // Gate table (difflogic order); gate 0 == 0 so v[0] unused.
    float c1  = v[8] + v[9] + v[10] + v[11] + v[12] + v[13] + v[14] + v[15];
    float ca  = v[2] + v[3] + v[6] + v[7] - v[8] - v[9] - v[12] - v[13];
    float cb  = v[4] + v[5] + v[6] + v[7] - v[8] - v[9] - v[10] - v[11];
    float cab = v[1] - v[2] - v[4] - 2.0f * v[6] - v[7]
              + v[8] + 2.0f * v[9] + v[11] + v[13] - v[14];

    g_coef[o] = make_float4(c1, ca, cb, cab);
    g_idx[o]  = make_int2(idx_a[o], idx_b[o]);
}

// ---------------------------------------------------------------------------
// Kernel 2: gather + affine eval, software-pipelined over columns.
//   idx/coef prefetched 2 iterations ahead (L2 latency),
//   smem gathers prefetched 1 iteration ahead (LDS latency).
// ---------------------------------------------------------------------------
__global__ __launch_bounds__(THREADS, 1)
void logic_kernel(const float* __restrict__ x,
                  float*       __restrict__ out)
{
    extern __shared__ H8 sx[];  // sx[col].h[p] = rows {2p, 2p+1} of column col

    const int row0 = blockIdx.y * ROWS_PER_CTA;
    const int col0 = blockIdx.x * COLS_PER_CTA;
    const int lane = threadIdx.x & 31;
    const int warp = threadIdx.x >> 5;
    constexpr int NWARPS = THREADS / 32;

    // Transposed fp16 staging: per 32-column group, 8 coalesced row loads,
    // convert to half, one contiguous STS.128 per lane (conflict-free).
    const float* xb = x + (size_t)row0 * IN_DIM;
#pragma unroll
    for (int g = warp; g < IN_DIM / 32; g += NWARPS) {
        int col = g * 32 + lane;
        H8 v;
#pragma unroll
        for (int p = 0; p < 4; p++) {
            v.h[p] = make_half2(__float2half_rn(xb[(size_t)(2 * p + 0) * IN_DIM + col]),
                                __float2half_rn(xb[(size_t)(2 * p + 1) * IN_DIM + col]));
        }
        sx[col] = v;
    }
    __syncthreads();

    // -------- pipelined main loop --------
    const int cbase = col0 + threadIdx.x;

    // Prologue: idx/coef for c=0 and c=1; gathers for c=0.
    int2   id0 = g_idx [cbase];
    float4 cf0 = g_coef[cbase];
    int2   id1 = g_idx [cbase + THREADS];
    float4 cf1 = g_coef[cbase + THREADS];
    H8 a0 = sx[id0.x];
    H8 b0 = sx[id0.y];

#pragma unroll
    for (int c = 0; c < COLS_PER_THREAD; c++) {
        // Stage N+2: idx/coef fetch (L2).
        int2 id2; float4 cf2;
        if (c + 2 < COLS_PER_THREAD) {
            id2 = g_idx [cbase + (c + 2) * THREADS];
            cf2 = g_coef[cbase + (c + 2) * THREADS];
        }
        // Stage N+1: smem gathers.
        H8 a1, b1;
        if (c + 1 < COLS_PER_THREAD) {
            a1 = sx[id1.x];
            b1 = sx[id1.y];
        }

        // Stage N: compute + streaming stores.
        float* o0 = out + (size_t)row0 * OUT_DIM + (cbase + c * THREADS);
#pragma unroll
        for (int p = 0; p < 4; p++) {
            float2 af = __half22float2(a0.h[p]);
            float2 bf = __half22float2(b0.h[p]);
            __stcs(o0 + (size_t)(2 * p + 0) * OUT_DIM,
                   fmaf(cf0.w, af.x * bf.x, fmaf(cf0.z, bf.x, fmaf(cf0.y, af.x, cf0.x))));
            __stcs(o0 + (size_t)(2 * p + 1) * OUT_DIM,
                   fmaf(cf0.w, af.y * bf.y, fmaf(cf0.z, bf.y, fmaf(cf0.y, af.y, cf0.x))));
        }

        // Rotate pipeline registers.
        a0 = a1; b0 = b1;
        id0 = id1; cf0 = cf1;
        id1 = id2; cf1 = cf2;
    }
}

// ---------------------------------------------------------------------------
// Launch
// ---------------------------------------------------------------------------
extern "C" void kernel_launch(void* const* d_in, const int* in_sizes, int n_in,
                              void* d_out, int out_size)
{
    const float* x  = (const float*)d_in[0];   // [2048, 8192] f32
    const float* w  = (const float*)d_in[1];   // [16384, 16]  f32
    const int*   ia = (const int*)d_in[2];     // [16384] i32
    const int*   ib = (const int*)d_in[3];     // [16384] i32
    float*       out = (float*)d_out;          // [2048, 16384] f32

    coef_kernel<<<OUT_DIM / 256, 256>>>(w, ia, ib);

    cudaFuncSetAttribute(logic_kernel,
                         cudaFuncAttributeMaxDynamicSharedMemorySize, SMEM_BYTES);

    dim3 grid(OUT_DIM / COLS_PER_CTA, B_ROWS / ROWS_PER_CTA);  // (2, 256)
    logic_kernel<<<grid, THREADS, SMEM_BYTES>>>(x, out);
}

// round 6
// speedup vs baseline: 1.7735x; 1.2198x over previous
#include <cuda_runtime.h>
#include <cuda_fp16.h>

#define IN_DIM   8192
#define OUT_DIM  16384
#define B_ROWS   2048

constexpr int THREADS         = 1024;
constexpr int ROWS_PER_CTA    = 8;                        // 8 fp16 rows per 16B smem slot
constexpr int COLS_PER_CTA    = 16384;                    // whole output row per CTA
constexpr int COLS_PER_THREAD = COLS_PER_CTA / THREADS;   // 16
constexpr int SMEM_BYTES      = IN_DIM * ROWS_PER_CTA * 2;  // 128 KB

// 16-byte slot holding 8 fp16 batch rows of one input column.
struct alignas(16) H8 { half2 h[4]; };

// Precomputed per-output-column data.
__device__ float4   g_coef[OUT_DIM];   // out = c1 + ca*a + cb*b + cab*ab
__device__ unsigned g_idx [OUT_DIM];   // idx_a | (idx_b << 16)

// ---------------------------------------------------------------------------
// Kernel 1: softmax(weights) -> affine coefficients; pack idx pairs.
// ---------------------------------------------------------------------------
__global__ void coef_kernel(const float* __restrict__ w,
                            const int*   __restrict__ idx_a,
                            const int*   __restrict__ idx_b)
{
    int o = blockIdx.x * blockDim.x + threadIdx.x;
    if (o >= OUT_DIM) return;

    float v[16];
    float m = -1e30f;
#pragma unroll
    for (int i = 0; i < 16; i++) {
        v[i] = w[o * 16 + i];
        m = fmaxf(m, v[i]);
    }
    float s = 0.0f;
#pragma unroll
    for (int i = 0; i < 16; i++) {
        v[i] = expf(v[i] - m);
        s += v[i];
    }
    float inv = 1.0f / s;
#pragma unroll
    for (int i = 0; i < 16; i++) v[i] *= inv;

    // Gate table (difflogic order); gate 0 == 0 so v[0] unused.
    float c1  = v[8] + v[9] + v[10] + v[11] + v[12] + v[13] + v[14] + v[15];
    float ca  = v[2] + v[3] + v[6] + v[7] - v[8] - v[9] - v[12] - v[13];
    float cb  = v[4] + v[5] + v[6] + v[7] - v[8] - v[9] - v[10] - v[11];
    float cab = v[1] - v[2] - v[4] - 2.0f * v[6] - v[7]
              + v[8] + 2.0f * v[9] + v[11] + v[13] - v[14];

    g_coef[o] = make_float4(c1, ca, cb, cab);
    g_idx[o]  = (unsigned)idx_a[o] | ((unsigned)idx_b[o] << 16);
}

// ---------------------------------------------------------------------------
// Kernel 2: gather + affine eval. One CTA = 8 batch rows x ALL 16384 columns.
// Smem slab: sx[in_col] = 8 fp16 batch rows; one LDS.128 = 8 rows of a column.
// ---------------------------------------------------------------------------
__global__ __launch_bounds__(THREADS, 1)
void logic_kernel(const float* __restrict__ x,
                  float*       __restrict__ out)
{
    extern __shared__ H8 sx[];  // sx[col].h[p] = rows {2p, 2p+1} of column col

    const int row0 = blockIdx.x * ROWS_PER_CTA;
    const int lane = threadIdx.x & 31;
    const int warp = threadIdx.x >> 5;
    constexpr int NWARPS = THREADS / 32;

    // Transposed fp16 staging: per 32-column group, 8 coalesced row loads,
    // convert to half, one contiguous STS.128 per lane (conflict-free).
    const float* xb = x + (size_t)row0 * IN_DIM;
#pragma unroll
    for (int g = warp; g < IN_DIM / 32; g += NWARPS) {
        int col = g * 32 + lane;
        H8 v;
#pragma unroll
        for (int p = 0; p < 4; p++) {
            v.h[p] = make_half2(__float2half_rn(xb[(size_t)(2 * p + 0) * IN_DIM + col]),
                                __float2half_rn(xb[(size_t)(2 * p + 1) * IN_DIM + col]));
        }
        sx[col] = v;
    }
    __syncthreads();

#pragma unroll
    for (int c = 0; c < COLS_PER_THREAD; c++) {
        const int col = c * THREADS + threadIdx.x;
        const unsigned id = g_idx[col];
        const float4   cf = g_coef[col];

        const H8 a8 = sx[id & 0xFFFFu];   // 8 batch rows of a in one LDS.128
        const H8 b8 = sx[id >> 16];

        float* o0 = out + (size_t)row0 * OUT_DIM + col;
#pragma unroll
        for (int p = 0; p < 4; p++) {
            float2 af = __half22float2(a8.h[p]);
            float2 bf = __half22float2(b8.h[p]);
            __stcs(o0 + (size_t)(2 * p + 0) * OUT_DIM,
                   fmaf(cf.w, af.x * bf.x, fmaf(cf.z, bf.x, fmaf(cf.y, af.x, cf.x))));
            __stcs(o0 + (size_t)(2 * p + 1) * OUT_DIM,
                   fmaf(cf.w, af.y * bf.y, fmaf(cf.z, bf.y, fmaf(cf.y, af.y, cf.x))));
        }
    }
}

// ---------------------------------------------------------------------------
// Launch
// ---------------------------------------------------------------------------
extern "C" void kernel_launch(void* const* d_in, const int* in_sizes, int n_in,
                              void* d_out, int out_size)
{
    const float* x  = (const float*)d_in[0];   // [2048, 8192] f32
    const float* w  = (const float*)d_in[1];   // [16384, 16]  f32
    const int*   ia = (const int*)d_in[2];     // [16384] i32
    const int*   ib = (const int*)d_in[3];     // [16384] i32
    float*       out = (float*)d_out;          // [2048, 16384] f32

    coef_kernel<<<OUT_DIM / 256, 256>>>(w, ia, ib);

    cudaFuncSetAttribute(logic_kernel,
                         cudaFuncAttributeMaxDynamicSharedMemorySize, SMEM_BYTES);

    logic_kernel<<<B_ROWS / ROWS_PER_CTA, THREADS, SMEM_BYTES>>>(x, out);  // 256 CTAs
}

// round 7
// speedup vs baseline: 1.8545x; 1.0457x over previous
#include <cuda_runtime.h>
#include <cuda_fp16.h>

#define IN_DIM   8192
#define OUT_DIM  16384
#define B_ROWS   2048

constexpr int THREADS         = 1024;
constexpr int ROWS_PER_CTA    = 8;                        // 8 fp16 rows per 16B smem slot
constexpr int COLS_PER_CTA    = 16384;                    // whole output row per CTA
constexpr int COLS_PER_THREAD = COLS_PER_CTA / THREADS;   // 16
constexpr int SMEM_BYTES      = IN_DIM * ROWS_PER_CTA * 2;  // 128 KB

// 16-byte slot holding 8 fp16 batch rows of one input column.
struct alignas(16) H8 { half2 h[4]; };
// 8-byte fp16 coefficient quad: {c1, ca}, {cb, cab}.
struct alignas(8) CF4 { __half2 p01; __half2 p23; };

// Precomputed per-output-column data (SoA, 12 B/col total).
__device__ CF4      g_cf [OUT_DIM];   // out = c1 + ca*a + cb*b + cab*ab
__device__ unsigned g_idx[OUT_DIM];   // idx_a | (idx_b << 16)

// ---------------------------------------------------------------------------
// Kernel 1: softmax(weights) -> affine coefficients (fp16); pack idx pairs.
// ---------------------------------------------------------------------------
__global__ void coef_kernel(const float* __restrict__ w,
                            const int*   __restrict__ idx_a,
                            const int*   __restrict__ idx_b)
{
    int o = blockIdx.x * blockDim.x + threadIdx.x;
    if (o >= OUT_DIM) return;

    // Vector loads: 4 x LDG.128 per thread.
    const float4* w4 = reinterpret_cast<const float4*>(w + (size_t)o * 16);
    float v[16];
#pragma unroll
    for (int q = 0; q < 4; q++) {
        float4 t = w4[q];
        v[4 * q + 0] = t.x; v[4 * q + 1] = t.y;
        v[4 * q + 2] = t.z; v[4 * q + 3] = t.w;
    }

    float m = -1e30f;
#pragma unroll
    for (int i = 0; i < 16; i++) m = fmaxf(m, v[i]);
    float s = 0.0f;
#pragma unroll
    for (int i = 0; i < 16; i++) {
        v[i] = __expf(v[i] - m);
        s += v[i];
    }
    float inv = 1.0f / s;
#pragma unroll
    for (int i = 0; i < 16; i++) v[i] *= inv;

    // Gate table (difflogic order); gate 0 == 0 so v[0] unused.
    float c1  = v[8] + v[9] + v[10] + v[11] + v[12] + v[13] + v[14] + v[15];
    float ca  = v[2] + v[3] + v[6] + v[7] - v[8] - v[9] - v[12] - v[13];
    float cb  = v[4] + v[5] + v[6] + v[7] - v[8] - v[9] - v[10] - v[11];
    float cab = v[1] - v[2] - v[4] - 2.0f * v[6] - v[7]
              + v[8] + 2.0f * v[9] + v[11] + v[13] - v[14];

    CF4 cf;
    cf.p01 = __floats2half2_rn(c1, ca);
    cf.p23 = __floats2half2_rn(cb, cab);
    g_cf[o]  = cf;
    g_idx[o] = (unsigned)idx_a[o] | ((unsigned)idx_b[o] << 16);
}

// ---------------------------------------------------------------------------
// Kernel 2: gather + affine eval. One CTA = 8 batch rows x ALL 16384 columns.
// Smem slab: sx[in_col] = 8 fp16 batch rows; one LDS.128 = 8 rows of a column.
// ---------------------------------------------------------------------------
__global__ __launch_bounds__(THREADS, 1)
void logic_kernel(const float* __restrict__ x,
                  float*       __restrict__ out)
{
    extern __shared__ H8 sx[];  // sx[col].h[p] = rows {2p, 2p+1} of column col

    const int row0 = blockIdx.x * ROWS_PER_CTA;
    const int lane = threadIdx.x & 31;
    const int warp = threadIdx.x >> 5;
    constexpr int NWARPS = THREADS / 32;

    // Transposed fp16 staging: per 32-column group, 8 coalesced row loads,
    // convert to half, one contiguous STS.128 per lane (conflict-free).
    const float* xb = x + (size_t)row0 * IN_DIM;
#pragma unroll
    for (int g = warp; g < IN_DIM / 32; g += NWARPS) {
        int col = g * 32 + lane;
        H8 v;
#pragma unroll
        for (int p = 0; p < 4; p++) {
            v.h[p] = make_half2(__float2half_rn(xb[(size_t)(2 * p + 0) * IN_DIM + col]),
                                __float2half_rn(xb[(size_t)(2 * p + 1) * IN_DIM + col]));
        }
        sx[col] = v;
    }
    __syncthreads();

#pragma unroll
    for (int c = 0; c < COLS_PER_THREAD; c++) {
        const int col = c * THREADS + threadIdx.x;
        const unsigned id = g_idx[col];
        const CF4      cw = g_cf[col];

        const float2 c01 = __half22float2(cw.p01);  // {c1, ca}
        const float2 c23 = __half22float2(cw.p23);  // {cb, cab}

        const H8 a8 = sx[id & 0xFFFFu];   // 8 batch rows of a in one LDS.128
        const H8 b8 = sx[id >> 16];

        float* o0 = out + (size_t)row0 * OUT_DIM + col;
#pragma unroll
        for (int p = 0; p < 4; p++) {
            float2 af = __half22float2(a8.h[p]);
            float2 bf = __half22float2(b8.h[p]);
            __stcs(o0 + (size_t)(2 * p + 0) * OUT_DIM,
                   fmaf(c23.y, af.x * bf.x, fmaf(c23.x, bf.x, fmaf(c01.y, af.x, c01.x))));
            __stcs(o0 + (size_t)(2 * p + 1) * OUT_DIM,
                   fmaf(c23.y, af.y * bf.y, fmaf(c23.x, bf.y, fmaf(c01.y, af.y, c01.x))));
        }
    }
}

// ---------------------------------------------------------------------------
// Launch
// ---------------------------------------------------------------------------
extern "C" void kernel_launch(void* const* d_in, const int* in_sizes, int n_in,
                              void* d_out, int out_size)
{
    const float* x  = (const float*)d_in[0];   // [2048, 8192] f32
    const float* w  = (const float*)d_in[1];   // [16384, 16]  f32
    const int*   ia = (const int*)d_in[2];     // [16384] i32
    const int*   ib = (const int*)d_in[3];     // [16384] i32
    float*       out = (float*)d_out;          // [2048, 16384] f32

    coef_kernel<<<OUT_DIM / 256, 256>>>(w, ia, ib);

    cudaFuncSetAttribute(logic_kernel,
                         cudaFuncAttributeMaxDynamicSharedMemorySize, SMEM_BYTES);

    logic_kernel<<<B_ROWS / ROWS_PER_CTA, THREADS, SMEM_BYTES>>>(x, out);  // 256 CTAs
}

// round 8
// speedup vs baseline: 1.8663x; 1.0064x over previous
#include <cuda_runtime.h>
#include <cuda_fp16.h>

#define IN_DIM   8192
#define OUT_DIM  16384
#define B_ROWS   2048

constexpr int THREADS         = 1024;
constexpr int SLAB_ROWS       = 8;                        // fp16 rows per smem slot
constexpr int PHASES          = 2;                        // row-slabs per CTA
constexpr int ROWS_PER_CTA    = SLAB_ROWS * PHASES;       // 16
constexpr int COLS_PER_THREAD = OUT_DIM / THREADS;        // 16
constexpr int SLAB_BYTES      = IN_DIM * SLAB_ROWS * 2;   // 128 KB
constexpr int IDX_BYTES       = OUT_DIM * 4;              // 64 KB
constexpr int SMEM_BYTES      = SLAB_BYTES + IDX_BYTES;   // 192 KB

// 16-byte slot holding 8 fp16 batch rows of one input column.
struct alignas(16) H8 { half2 h[4]; };
// 8-byte fp16 coefficient quad: {c1, ca}, {cb, cab}.
struct alignas(8) CF4 { __half2 p01; __half2 p23; };

// Precomputed per-output-column data.
__device__ CF4      g_cf [OUT_DIM];   // out = c1 + ca*a + cb*b + cab*ab
__device__ unsigned g_idx[OUT_DIM];   // idx_a | (idx_b << 16)

// ---------------------------------------------------------------------------
// Kernel 1: softmax(weights) -> affine coefficients (fp16); pack idx pairs.
// ---------------------------------------------------------------------------
__global__ void coef_kernel(const float* __restrict__ w,
                            const int*   __restrict__ idx_a,
                            const int*   __restrict__ idx_b)
{
    int o = blockIdx.x * blockDim.x + threadIdx.x;
    if (o >= OUT_DIM) return;

    const float4* w4 = reinterpret_cast<const float4*>(w + (size_t)o * 16);
    float v[16];
#pragma unroll
    for (int q = 0; q < 4; q++) {
        float4 t = w4[q];
        v[4 * q + 0] = t.x; v[4 * q + 1] = t.y;
        v[4 * q + 2] = t.z; v[4 * q + 3] = t.w;
    }

    float m = -1e30f;
#pragma unroll
    for (int i = 0; i < 16; i++) m = fmaxf(m, v[i]);
    float s = 0.0f;
#pragma unroll
    for (int i = 0; i < 16; i++) {
        v[i] = __expf(v[i] - m);
        s += v[i];
    }
    float inv = 1.0f / s;
#pragma unroll
    for (int i = 0; i < 16; i++) v[i] *= inv;

    // Gate table (difflogic order); gate 0 == 0 so v[0] unused.
    float c1  = v[8] + v[9] + v[10] + v[11] + v[12] + v[13] + v[14] + v[15];
    float ca  = v[2] + v[3] + v[6] + v[7] - v[8] - v[9] - v[12] - v[13];
    float cb  = v[4] + v[5] + v[6] + v[7] - v[8] - v[9] - v[10] - v[11];
    float cab = v[1] - v[2] - v[4] - 2.0f * v[6] - v[7]
              + v[8] + 2.0f * v[9] + v[11] + v[13] - v[14];

    CF4 cf;
    cf.p01 = __floats2half2_rn(c1, ca);
    cf.p23 = __floats2half2_rn(cb, cab);
    g_cf[o]  = cf;
    g_idx[o] = (unsigned)idx_a[o] | ((unsigned)idx_b[o] << 16);
}

// ---------------------------------------------------------------------------
// Kernel 2: one CTA = 16 batch rows x all 16384 cols, as two 8-row phases.
// idx lives in smem (read from L2 once per CTA); slab re-staged per phase.
// ---------------------------------------------------------------------------
__global__ __launch_bounds__(THREADS, 1)
void logic_kernel(const float* __restrict__ x,
                  float*       __restrict__ out)
{
    extern __shared__ char smem[];
    H8*       sx   = reinterpret_cast<H8*>(smem);                 // [IN_DIM]
    unsigned* sidx = reinterpret_cast<unsigned*>(smem + SLAB_BYTES);  // [OUT_DIM]

    const int lane = threadIdx.x & 31;
    const int warp = threadIdx.x >> 5;
    constexpr int NWARPS = THREADS / 32;

    // Load packed idx into smem once (coalesced uint4).
    {
        const uint4* gi = reinterpret_cast<const uint4*>(g_idx);
        uint4*       si = reinterpret_cast<uint4*>(sidx);
#pragma unroll
        for (int i = threadIdx.x; i < OUT_DIM / 4; i += THREADS)
            si[i] = gi[i];
    }

#pragma unroll
    for (int ph = 0; ph < PHASES; ph++) {
        const int row0 = blockIdx.x * ROWS_PER_CTA + ph * SLAB_ROWS;

        __syncthreads();  // previous phase's reads done (and idx ready on ph=0)

        // Transposed fp16 staging: per 32-column group, 8 coalesced row loads,
        // convert to half, one contiguous STS.128 per lane (conflict-free).
        const float* xb = x + (size_t)row0 * IN_DIM;
#pragma unroll
        for (int g = warp; g < IN_DIM / 32; g += NWARPS) {
            int col = g * 32 + lane;
            H8 v;
#pragma unroll
            for (int p = 0; p < 4; p++) {
                v.h[p] = make_half2(__float2half_rn(xb[(size_t)(2 * p + 0) * IN_DIM + col]),
                                    __float2half_rn(xb[(size_t)(2 * p + 1) * IN_DIM + col]));
            }
            sx[col] = v;
        }
        __syncthreads();

#pragma unroll
        for (int c = 0; c < COLS_PER_THREAD; c++) {
            const int col = c * THREADS + threadIdx.x;
            const unsigned id = sidx[col];
            const CF4      cw = g_cf[col];

            const float2 c01 = __half22float2(cw.p01);  // {c1, ca}
            const float2 c23 = __half22float2(cw.p23);  // {cb, cab}

            const H8 a8 = sx[id & 0xFFFFu];   // 8 batch rows in one LDS.128
            const H8 b8 = sx[id >> 16];

            float* o0 = out + (size_t)row0 * OUT_DIM + col;
#pragma unroll
            for (int p = 0; p < 4; p++) {
                float2 af = __half22float2(a8.h[p]);
                float2 bf = __half22float2(b8.h[p]);
                __stcs(o0 + (size_t)(2 * p + 0) * OUT_DIM,
                       fmaf(c23.y, af.x * bf.x, fmaf(c23.x, bf.x, fmaf(c01.y, af.x, c01.x))));
                __stcs(o0 + (size_t)(2 * p + 1) * OUT_DIM,
                       fmaf(c23.y, af.y * bf.y, fmaf(c23.x, bf.y, fmaf(c01.y, af.y, c01.x))));
            }
        }
    }
}

// ---------------------------------------------------------------------------
// Launch
// ---------------------------------------------------------------------------
extern "C" void kernel_launch(void* const* d_in, const int* in_sizes, int n_in,
                              void* d_out, int out_size)
{
    const float* x  = (const float*)d_in[0];   // [2048, 8192] f32
    const float* w  = (const float*)d_in[1];   // [16384, 16]  f32
    const int*   ia = (const int*)d_in[2];     // [16384] i32
    const int*   ib = (const int*)d_in[3];     // [16384] i32
    float*       out = (float*)d_out;          // [2048, 16384] f32

    coef_kernel<<<OUT_DIM / 128, 128>>>(w, ia, ib);

    cudaFuncSetAttribute(logic_kernel,
                         cudaFuncAttributeMaxDynamicSharedMemorySize, SMEM_BYTES);

    logic_kernel<<<B_ROWS / ROWS_PER_CTA, THREADS, SMEM_BYTES>>>(x, out);  // 128 CTAs
}

// round 9
// speedup vs baseline: 1.8716x; 1.0028x over previous
#include <cuda_runtime.h>
#include <cuda_fp16.h>

#define IN_DIM   8192
#define OUT_DIM  16384
#define B_ROWS   2048

constexpr int THREADS         = 1024;
constexpr int SLAB_ROWS       = 8;                        // fp16 rows per smem slot
constexpr int PHASES          = 2;                        // row-slabs per CTA
constexpr int ROWS_PER_CTA    = SLAB_ROWS * PHASES;       // 16
constexpr int COLS_PER_THREAD = OUT_DIM / THREADS;        // 16
constexpr int SLAB_BYTES      = IN_DIM * SLAB_ROWS * 2;   // 128 KB
constexpr int IDX_BYTES       = OUT_DIM * 4;              // 64 KB
constexpr int SMEM_BYTES      = SLAB_BYTES + IDX_BYTES;   // 192 KB

// 16-byte slot holding 8 fp16 batch rows of one input column.
struct alignas(16) H8 { half2 h[4]; };
// 8-byte fp16 coefficient quad: {c1, ca}, {cb, cab}.
struct alignas(8) CF4 { __half2 p01; __half2 p23; };

// Precomputed per-output-column data.
__device__ CF4      g_cf [OUT_DIM];   // out = c1 + ca*a + cb*b + cab*ab
__device__ unsigned g_idx[OUT_DIM];   // idx_a | (idx_b << 16)

// ---------------------------------------------------------------------------
// Kernel 1: softmax(weights) -> affine coefficients (fp16); pack idx pairs.
// Triggers PDL immediately so logic_kernel can start staging concurrently.
// ---------------------------------------------------------------------------
__global__ void coef_kernel(const float* __restrict__ w,
                            const int*   __restrict__ idx_a,
                            const int*   __restrict__ idx_b)
{
    cudaTriggerProgrammaticLaunchCompletion();

    int o = blockIdx.x * blockDim.x + threadIdx.x;
    if (o >= OUT_DIM) return;

    const float4* w4 = reinterpret_cast<const float4*>(w + (size_t)o * 16);
    float v[16];
#pragma unroll
    for (int q = 0; q < 4; q++) {
        float4 t = w4[q];
        v[4 * q + 0] = t.x; v[4 * q + 1] = t.y;
        v[4 * q + 2] = t.z; v[4 * q + 3] = t.w;
    }

    float m = -1e30f;
#pragma unroll
    for (int i = 0; i < 16; i++) m = fmaxf(m, v[i]);
    float s = 0.0f;
#pragma unroll
    for (int i = 0; i < 16; i++) {
        v[i] = __expf(v[i] - m);
        s += v[i];
    }
    float inv = 1.0f / s;
#pragma unroll
    for (int i = 0; i < 16; i++) v[i] *= inv;

    // Gate table (difflogic order); gate 0 == 0 so v[0] unused.
    float c1  = v[8] + v[9] + v[10] + v[11] + v[12] + v[13] + v[14] + v[15];
    float ca  = v[2] + v[3] + v[6] + v[7] - v[8] - v[9] - v[12] - v[13];
    float cb  = v[4] + v[5] + v[6] + v[7] - v[8] - v[9] - v[10] - v[11];
    float cab = v[1] - v[2] - v[4] - 2.0f * v[6] - v[7]
              + v[8] + 2.0f * v[9] + v[11] + v[13] - v[14];

    CF4 cf;
    cf.p01 = __floats2half2_rn(c1, ca);
    cf.p23 = __floats2half2_rn(cb, cab);
    g_cf[o]  = cf;
    g_idx[o] = (unsigned)idx_a[o] | ((unsigned)idx_b[o] << 16);
}

// ---------------------------------------------------------------------------
// Kernel 2: one CTA = 16 batch rows x all 16384 cols, as two 8-row phases.
// Phase-0 x staging overlaps coef_kernel via PDL; gridDependencySynchronize
// gates the first read of g_idx/g_cf.
// ---------------------------------------------------------------------------
__global__ __launch_bounds__(THREADS, 1)
void logic_kernel(const float* __restrict__ x,
                  float*       __restrict__ out)
{
    extern __shared__ char smem[];
    H8*       sx   = reinterpret_cast<H8*>(smem);                     // [IN_DIM]
    unsigned* sidx = reinterpret_cast<unsigned*>(smem + SLAB_BYTES);  // [OUT_DIM]

    const int lane = threadIdx.x & 31;
    const int warp = threadIdx.x >> 5;
    constexpr int NWARPS = THREADS / 32;

#pragma unroll
    for (int ph = 0; ph < PHASES; ph++) {
        const int row0 = blockIdx.x * ROWS_PER_CTA + ph * SLAB_ROWS;

        if (ph > 0) __syncthreads();  // previous phase's smem reads done

        // Transposed fp16 staging: per 32-column group, 8 coalesced row loads,
        // convert to half, one contiguous STS.128 per lane (conflict-free).
        // Phase 0 runs while coef_kernel may still be in flight (PDL).
        const float* xb = x + (size_t)row0 * IN_DIM;
#pragma unroll
        for (int g = warp; g < IN_DIM / 32; g += NWARPS) {
            int col = g * 32 + lane;
            H8 v;
#pragma unroll
            for (int p = 0; p < 4; p++) {
                v.h[p] = make_half2(__float2half_rn(xb[(size_t)(2 * p + 0) * IN_DIM + col]),
                                    __float2half_rn(xb[(size_t)(2 * p + 1) * IN_DIM + col]));
            }
            sx[col] = v;
        }

        if (ph == 0) {
            // Wait for coef_kernel's writes, then pull idx into smem.
            cudaGridDependencySynchronize();
            const uint4* gi = reinterpret_cast<const uint4*>(g_idx);
            uint4*       si = reinterpret_cast<uint4*>(sidx);
#pragma unroll
            for (int i = threadIdx.x; i < OUT_DIM / 4; i += THREADS)
                si[i] = gi[i];
        }
        __syncthreads();

#pragma unroll
        for (int c = 0; c < COLS_PER_THREAD; c++) {
            const int col = c * THREADS + threadIdx.x;
            const unsigned id = sidx[col];
            const CF4      cw = g_cf[col];

            const float2 c01 = __half22float2(cw.p01);  // {c1, ca}
            const float2 c23 = __half22float2(cw.p23);  // {cb, cab}

            const H8 a8 = sx[id & 0xFFFFu];   // 8 batch rows in one LDS.128
            const H8 b8 = sx[id >> 16];

            float* o0 = out + (size_t)row0 * OUT_DIM + col;
#pragma unroll
            for (int p = 0; p < 4; p++) {
                float2 af = __half22float2(a8.h[p]);
                float2 bf = __half22float2(b8.h[p]);
                __stcs(o0 + (size_t)(2 * p + 0) * OUT_DIM,
                       fmaf(c23.y, af.x * bf.x, fmaf(c23.x, bf.x, fmaf(c01.y, af.x, c01.x))));
                __stcs(o0 + (size_t)(2 * p + 1) * OUT_DIM,
                       fmaf(c23.y, af.y * bf.y, fmaf(c23.x, bf.y, fmaf(c01.y, af.y, c01.x))));
            }
        }
    }
}

// ---------------------------------------------------------------------------
// Launch: coef_kernel, then logic_kernel with PDL so its staging overlaps.
// ---------------------------------------------------------------------------
extern "C" void kernel_launch(void* const* d_in, const int* in_sizes, int n_in,
                              void* d_out, int out_size)
{
    const float* x  = (const float*)d_in[0];   // [2048, 8192] f32
    const float* w  = (const float*)d_in[1];   // [16384, 16]  f32
    const int*   ia = (const int*)d_in[2];     // [16384] i32
    const int*   ib = (const int*)d_in[3];     // [16384] i32
    float*       out = (float*)d_out;          // [2048, 16384] f32

    coef_kernel<<<OUT_DIM / 128, 128>>>(w, ia, ib);

    cudaFuncSetAttribute(logic_kernel,
                         cudaFuncAttributeMaxDynamicSharedMemorySize, SMEM_BYTES);

    cudaLaunchConfig_t cfg = {};
    cfg.gridDim         = dim3(B_ROWS / ROWS_PER_CTA);   // 128 CTAs
    cfg.blockDim        = dim3(THREADS);
    cfg.dynamicSmemBytes = SMEM_BYTES;
    cudaLaunchAttribute attrs[1];
    attrs[0].id = cudaLaunchAttributeProgrammaticStreamSerialization;
    attrs[0].val.programmaticStreamSerializationAllowed = 1;
    cfg.attrs    = attrs;
    cfg.numAttrs = 1;

    cudaLaunchKernelEx(&cfg, logic_kernel, x, out);
}